// round 16
// baseline (speedup 1.0000x reference)
#include <cuda_runtime.h>
#include <cuda_bf16.h>
#include <cuda_fp16.h>
#include <cstdint>

// Problem constants
#define BB 4
#define SS 2048
#define DD 1024
#define HH 16
#define DHH 64
#define BSROWS (BB * SS)          // 8192

// ---------------------------------------------------------------------------
// Device-global scratch (allocation-free). All single fp16.
// ---------------------------------------------------------------------------
__device__ __half g_x[(size_t)BSROWS * DD];
__device__ __half g_q[(size_t)BSROWS * DD];
__device__ __half g_k[(size_t)BSROWS * DD];
__device__ __half g_v[(size_t)BSROWS * DD];
__device__ __half g_a[(size_t)BSROWS * DD];
__device__ __half g_wt[4 * (size_t)DD * DD];   // W^T [n][k], single fp16

#define LOG2E 1.4426950408889634f

// ---------------------------------------------------------------------------
// Helpers
// ---------------------------------------------------------------------------
__device__ __forceinline__ void mma_f16(float* c, const unsigned* a, const unsigned* b) {
    asm volatile(
        "mma.sync.aligned.m16n8k16.row.col.f32.f16.f16.f32 "
        "{%0,%1,%2,%3}, {%4,%5,%6,%7}, {%8,%9}, {%0,%1,%2,%3};\n"
        : "+f"(c[0]), "+f"(c[1]), "+f"(c[2]), "+f"(c[3])
        : "r"(a[0]), "r"(a[1]), "r"(a[2]), "r"(a[3]),
          "r"(b[0]), "r"(b[1]));
}

__device__ __forceinline__ void ldm_x4(unsigned* r, uint32_t addr) {
    asm volatile("ldmatrix.sync.aligned.m8n8.x4.shared.b16 {%0,%1,%2,%3}, [%4];"
        : "=r"(r[0]), "=r"(r[1]), "=r"(r[2]), "=r"(r[3]) : "r"(addr));
}
__device__ __forceinline__ void ldm_x4t(unsigned* r, uint32_t addr) {
    asm volatile("ldmatrix.sync.aligned.m8n8.x4.trans.shared.b16 {%0,%1,%2,%3}, [%4];"
        : "=r"(r[0]), "=r"(r[1]), "=r"(r[2]), "=r"(r[3]) : "r"(addr));
}

// f32 pair -> f16x2 (hi arg -> upper half)
__device__ __forceinline__ unsigned f16x2_of(float hi, float lo) {
    unsigned r;
    asm("cvt.rn.f16x2.f32 %0, %1, %2;" : "=r"(r) : "f"(hi), "f"(lo));
    return r;
}
__device__ __forceinline__ float ex2f(float x) {
    float r;
    asm("ex2.approx.ftz.f32 %0, %1;" : "=f"(r) : "f"(x));
    return r;
}

__device__ __forceinline__ void cpa16(void* s, const void* g) {
    unsigned sa = (unsigned)__cvta_generic_to_shared(s);
    asm volatile("cp.async.cg.shared.global [%0], [%1], 16;\n" :: "r"(sa), "l"(g));
}
__device__ __forceinline__ void cpa4(void* s, const void* g) {
    unsigned sa = (unsigned)__cvta_generic_to_shared(s);
    asm volatile("cp.async.ca.shared.global [%0], [%1], 4;\n" :: "r"(sa), "l"(g));
}
__device__ __forceinline__ void cpa_commit() {
    asm volatile("cp.async.commit_group;\n");
}
template <int N>
__device__ __forceinline__ void cpa_wait() {
    asm volatile("cp.async.wait_group %0;\n" :: "n"(N));
}
__device__ __forceinline__ uint32_t smem_u32(const void* p) {
    return (uint32_t)__cvta_generic_to_shared(p);
}

// ---------------------------------------------------------------------------
// Prep: x fp32 -> single fp16
// ---------------------------------------------------------------------------
__global__ __launch_bounds__(256)
void split_src(const float* __restrict__ x)
{
    int i = blockIdx.x * 256 + threadIdx.x;            // over float4s: 2M
    float4 v = reinterpret_cast<const float4*>(x)[i];
    uint2 u;
    u.x = f16x2_of(v.y, v.x);
    u.y = f16x2_of(v.w, v.z);
    reinterpret_cast<uint2*>(g_x)[i] = u;
}

// ---------------------------------------------------------------------------
// Prep: transpose all 4 W [k][n] fp32 -> g_wt[z] as [n][k] single fp16
// ---------------------------------------------------------------------------
__global__ __launch_bounds__(256)
void wsplit_all(const float* __restrict__ W0, const float* __restrict__ W1,
                const float* __restrict__ W2, const float* __restrict__ W3)
{
    const int widx = blockIdx.z;
    const float* W = (widx == 0) ? W0 : (widx == 1) ? W1 : (widx == 2) ? W2 : W3;
    __shared__ float t[32][33];
    const int kb = blockIdx.x * 32, nb = blockIdx.y * 32;
    const int r = threadIdx.x >> 3, c4 = (threadIdx.x & 7) * 4;
    float4 v = *reinterpret_cast<const float4*>(W + (size_t)(kb + r) * DD + nb + c4);
    t[r][c4 + 0] = v.x; t[r][c4 + 1] = v.y; t[r][c4 + 2] = v.z; t[r][c4 + 3] = v.w;
    __syncthreads();
    __half* oh = g_wt + (size_t)widx * DD * DD;
    uint2 uh;
    uh.x = f16x2_of(t[c4 + 1][r], t[c4 + 0][r]);
    uh.y = f16x2_of(t[c4 + 3][r], t[c4 + 2][r]);
    size_t o = (size_t)(nb + r) * DD + kb + c4;
    *reinterpret_cast<uint2*>(oh + o) = uh;
}

// ---------------------------------------------------------------------------
// GEMM (single fp16, m16n8k16 + ldmatrix): C = A * W^T' + bias, M=8192, N=K=1024
// CTA tile 128x128, 8 warps (4 M x 2 N), warp tile 32x64 (64-reg acc).
// KS=64, 3-STAGE cp.async pipeline (distance-2 prefetch, wait<1> in steady
// state) — hides a full stage of load latency now that math is 1-term.
// 2 CTAs/SM (smem 110.6 KB).
// mode -1: md=blockIdx.z (Q scaled 1/8; K, V single fp16 out)
// mode  3: A=g_a (attended), out fp32 to outF
// ---------------------------------------------------------------------------
#define KS 64
#define AST 72
#define NSTG 3
#define STAGE (128 * AST)                    // halves per array per stage = 9216
#define SLAB (NSTG * STAGE)                  // halves per array = 27648
#define GEMM_SMEM (2 * SLAB * 2)             // 110592 bytes (sA, sB)

__global__ __launch_bounds__(256, 2)
void gemm_k(const float* __restrict__ b0, const float* __restrict__ b1,
            const float* __restrict__ b2, float* __restrict__ outF, int mode)
{
    const int md = (mode < 0) ? (int)blockIdx.z : mode;
    const __half* A = (md < 3) ? g_x : g_a;
    const __half* Wh = g_wt + (size_t)md * DD * DD;
    const float* bias = (md == 1) ? b1 : (md == 2) ? b2 : b0;
    const float scale = (md == 0) ? 0.125f : 1.0f;

    extern __shared__ __half sm[];
    __half* sA = sm;
    __half* sB = sm + SLAB;
    const uint32_t uA = smem_u32(sA);
    const uint32_t uB = smem_u32(sB);

    const int tid  = threadIdx.x;
    const int lane = tid & 31;
    const int warp = tid >> 5;
    const int wm = warp & 3, wn = warp >> 2;
    const int cm = blockIdx.x * 128, cn = blockIdx.y * 128;
    const int rq = lane >> 2, cq = lane & 3;

    // ldmatrix lane->row mappings
    const int a_r = lane & 15, a_k = (lane >> 4) * 8;               // A x4
    const int b_n = ((lane >> 3) & 1) * 8 + (lane & 7);             // B x4 (pair of n-tiles)
    const int b_k = (lane >> 4) * 8;

    // stage kt (64 k-columns) into buffer buf
    auto issue = [&](int kt, int buf) {
        const int k0 = kt * KS;
        #pragma unroll
        for (int i = 0; i < 4; i++) {                // A: 128 rows
            int idx = i * 256 + tid;
            int r = idx >> 3, c8 = (idx & 7) * 8;
            size_t ga = (size_t)(cm + r) * DD + k0 + c8;
            int so = buf * STAGE + r * AST + c8;
            cpa16(&sA[so], A + ga);
        }
        #pragma unroll
        for (int i = 0; i < 4; i++) {                // B: 128 rows
            int idx = i * 256 + tid;
            int r = idx >> 3, c8 = (idx & 7) * 8;
            size_t gb = (size_t)(cn + r) * DD + k0 + c8;
            int so = buf * STAGE + r * AST + c8;
            cpa16(&sB[so], Wh + gb);
        }
        cpa_commit();
    };

    float acc[2][8][4];
    #pragma unroll
    for (int mt = 0; mt < 2; mt++)
        #pragma unroll
        for (int nt = 0; nt < 8; nt++)
            #pragma unroll
            for (int j = 0; j < 4; j++) acc[mt][nt][j] = 0.f;

    const int NK = DD / KS;  // 16
    issue(0, 0);
    issue(1, 1);

    int cur = 0;
    for (int kt = 0; kt < NK; ++kt) {
        // stage kt complete; stage kt+1 may stay in flight (except final iter)
        if (kt + 1 < NK) cpa_wait<1>();
        else             cpa_wait<0>();
        __syncthreads();            // data visible; readers of buffer (kt+2)%3 retired
        if (kt + 2 < NK) issue(kt + 2, (cur + 2 >= NSTG) ? cur + 2 - NSTG : cur + 2);

        const uint32_t bufOff = (uint32_t)(cur * STAGE * 2);
        const uint32_t abase = uA + bufOff + (uint32_t)(((wm * 32 + a_r) * AST + a_k) * 2);
        const uint32_t bbase = uB + bufOff + (uint32_t)(((wn * 64 + b_n) * AST + b_k) * 2);
        #pragma unroll
        for (int ch = 0; ch < 4; ++ch) {
            const uint32_t kc2 = (uint32_t)(ch * 32);   // 16 halves per chunk
            unsigned ah[2][4];
            #pragma unroll
            for (int mt = 0; mt < 2; mt++)
                ldm_x4(ah[mt], abase + (uint32_t)(mt * 16 * AST * 2) + kc2);
            #pragma unroll
            for (int ntp = 0; ntp < 4; ntp++) {
                unsigned kf[4];
                ldm_x4(kf, bbase + (uint32_t)(ntp * 16 * AST * 2) + kc2);
                unsigned bb0[2] = {kf[0], kf[2]}, bb1[2] = {kf[1], kf[3]};
                mma_f16(acc[0][2 * ntp],     ah[0], bb0);
                mma_f16(acc[1][2 * ntp],     ah[1], bb0);
                mma_f16(acc[0][2 * ntp + 1], ah[0], bb1);
                mma_f16(acc[1][2 * ntp + 1], ah[1], bb1);
            }
        }
        cur = (cur + 1 >= NSTG) ? 0 : cur + 1;
    }

    // epilogue
    #pragma unroll
    for (int mt = 0; mt < 2; mt++) {
        int r = cm + wm * 32 + mt * 16 + rq;
        #pragma unroll
        for (int nt = 0; nt < 8; nt++) {
            int c = cn + wn * 64 + nt * 8 + cq * 2;
            float bb0 = bias[c], bb1 = bias[c + 1];
            float v0 = (acc[mt][nt][0] + bb0) * scale;
            float v1 = (acc[mt][nt][1] + bb1) * scale;
            float v2 = (acc[mt][nt][2] + bb0) * scale;
            float v3 = (acc[mt][nt][3] + bb1) * scale;
            if (md == 3) {
                *reinterpret_cast<float2*>(outF + (size_t)r * DD + c) = make_float2(v0, v1);
                *reinterpret_cast<float2*>(outF + (size_t)(r + 8) * DD + c) = make_float2(v2, v3);
            } else {                // Q (pre-scaled) / K / V: single fp16
                __half* O = (md == 0) ? g_q : (md == 1) ? g_k : g_v;
                *reinterpret_cast<unsigned*>(O + (size_t)r * DD + c) = f16x2_of(v1, v0);
                *reinterpret_cast<unsigned*>(O + (size_t)(r + 8) * DD + c) = f16x2_of(v3, v2);
            }
        }
    }
}

// ---------------------------------------------------------------------------
// Flash attention (UNCHANGED — near multi-pipe roofline).
// 128-row Q tiles, 8 warps. QK: fp16 x fp16. PV: fp16 P x fp16 V.
// smem halves: Q (128xFST) | K0,K1 | V0,V1 (64xFST) | Ms[2][64]
// ---------------------------------------------------------------------------
#define FST 72                                // smem k-stride (halves)
#define F64 (64 * FST)                        // halves per 64-row array
#define QFQ (128 * FST)                       // Q halves
#define KOFF QFQ
#define VOFF (QFQ + 2 * F64)
#define FLASH_SMEM ((QFQ + 4 * F64) * 2 + 2 * 64 * 4)   // 55808 bytes

__global__ __launch_bounds__(256, 2)
void flash_attn_kernel(const int* __restrict__ pmask)
{
    extern __shared__ __half fsm[];
    int* Ms0 = reinterpret_cast<int*>(fsm + QFQ + 4 * F64);
    const uint32_t uQ = smem_u32(fsm);

    const int tid = threadIdx.x, lane = tid & 31, warp = tid >> 5;
    const int qb = (int)(gridDim.x - 1) - (int)blockIdx.x;  // heavy tiles first
    const int bh = blockIdx.y;
    const int b = bh >> 4, h = bh & 15;
    const size_t head_off = ((size_t)b * SS) * DD + (size_t)h * DHH;
    const int nkb = 2 * qb + 2;               // 64-wide key blocks needed

    const int rq = lane >> 2, cq = lane & 3;
    const int row0 = warp * 16 + rq;

    // ldmatrix lane->row mappings
    const int a_r = lane & 15, a_k = (lane >> 4) * 8;      // Q (A, x4)
    const int b_n = ((lane >> 3) & 1) * 8 + (lane & 7);    // K (B, x4 pair)
    const int b_k = (lane >> 4) * 8;
    const int v_k = ((lane >> 3) & 1) * 8 + (lane & 7);    // V (B^T via x4.trans)
    const int v_n = (lane >> 4) * 8;

    auto issueKV = [&](int kb) {
        const int bsel = kb & 1;
        __half* KS_ = fsm + KOFF + F64 * bsel;
        __half* VS = fsm + VOFF + F64 * bsel;
        #pragma unroll
        for (int i = 0; i < 2; i++) {
            int idx = i * 256 + tid;
            int r = idx >> 3, c8 = (idx & 7) * 8;
            size_t g = head_off + (size_t)(kb * 64 + r) * DD + c8;
            cpa16(&KS_[r * FST + c8], g_k + g);
            cpa16(&VS[r * FST + c8], g_v + g);
        }
        if (tid < 64) cpa4(&Ms0[bsel * 64 + tid], pmask + b * SS + kb * 64 + tid);
        cpa_commit();
    };

    // Prologue: Q (128x64 single fp16) + K0/V0/mask0 in ONE group
    #pragma unroll
    for (int i = 0; i < 4; i++) {
        int idx = i * 256 + tid;
        int r = idx >> 3, c8 = (idx & 7) * 8;
        size_t g = head_off + (size_t)(qb * 128 + r) * DD + c8;
        cpa16(&fsm[r * FST + c8], g_q + g);
    }
    {
        __half* KS_ = fsm + KOFF;
        __half* VS = fsm + VOFF;
        #pragma unroll
        for (int i = 0; i < 2; i++) {
            int idx = i * 256 + tid;
            int r = idx >> 3, c8 = (idx & 7) * 8;
            size_t g = head_off + (size_t)r * DD + c8;
            cpa16(&KS_[r * FST + c8], g_k + g);
            cpa16(&VS[r * FST + c8], g_v + g);
        }
        if (tid < 64) cpa4(&Ms0[tid], pmask + b * SS + tid);
        cpa_commit();
    }

    float o[8][4];
    #pragma unroll
    for (int nt = 0; nt < 8; nt++)
        #pragma unroll
        for (int j = 0; j < 4; j++) o[nt][j] = 0.f;
    float m0 = -1e30f, m1 = -1e30f, l0 = 0.f, l1 = 0.f;

    const uint32_t qbase = uQ + (uint32_t)(((warp * 16 + a_r) * FST + a_k) * 2);

    for (int kb = 0; kb < nkb; ++kb) {
        cpa_wait<0>();
        __syncthreads();
        if (kb + 1 < nkb) issueKV(kb + 1);

        // warp-uniform skip: entire kv-block above this warp's rows
        if (kb * 64 > qb * 128 + warp * 16 + 15) continue;

        const uint32_t uKH = smem_u32(fsm + KOFF + F64 * (kb & 1));
        const uint32_t uVS = smem_u32(fsm + VOFF + F64 * (kb & 1));
        const int* Ms = Ms0 + (kb & 1) * 64;

        // mask fast-path detection (warp-uniform)
        unsigned mw0 = __ballot_sync(0xffffffffu, Ms[lane] != 0);
        unsigned mw1 = __ballot_sync(0xffffffffu, Ms[32 + lane] != 0);
        const bool needmask = ((mw0 & mw1) != 0xffffffffu) ||
                              (kb * 64 + 63 > qb * 128 + warp * 16);

        // --- S = Q K^T (warp: 16 x 64), single-term fp16 ---
        float sc[8][4];
        #pragma unroll
        for (int nt = 0; nt < 8; nt++)
            #pragma unroll
            for (int j = 0; j < 4; j++) sc[nt][j] = 0.f;

        const uint32_t kbase = uKH + (uint32_t)((b_n * FST + b_k) * 2);
        #pragma unroll
        for (int ch = 0; ch < 4; ++ch) {
            const uint32_t kc2 = (uint32_t)(ch * 32);
            unsigned ah[4];
            ldm_x4(ah, qbase + kc2);
            #pragma unroll
            for (int ntp = 0; ntp < 4; ntp++) {
                unsigned kf[4];
                ldm_x4(kf, kbase + (uint32_t)(ntp * 16 * FST * 2) + kc2);
                unsigned bb0[2] = {kf[0], kf[2]}, bb1[2] = {kf[1], kf[3]};
                mma_f16(sc[2 * ntp],     ah, bb0);
                mma_f16(sc[2 * ntp + 1], ah, bb1);
            }
        }

        // --- mask (slow path only; Q pre-scaled; sentinel -1e30) ---
        if (needmask) {
            const int gm0 = qb * 128 + row0, gm1 = gm0 + 8;
            #pragma unroll
            for (int nt = 0; nt < 8; nt++) {
                int nloc = nt * 8 + cq * 2;
                int gn = kb * 64 + nloc;
                #pragma unroll
                for (int j = 0; j < 2; j++) {
                    bool pv = (Ms[nloc + j] != 0);
                    sc[nt][j]     = (pv && (gn + j) <= gm0) ? sc[nt][j]     : -1e30f;
                    sc[nt][2 + j] = (pv && (gn + j) <= gm1) ? sc[nt][2 + j] : -1e30f;
                }
            }
        }

        // --- online softmax ---
        float mx0 = -1e30f, mx1 = -1e30f;
        #pragma unroll
        for (int nt = 0; nt < 8; nt++) {
            mx0 = fmaxf(mx0, fmaxf(sc[nt][0], sc[nt][1]));
            mx1 = fmaxf(mx1, fmaxf(sc[nt][2], sc[nt][3]));
        }
        mx0 = fmaxf(mx0, __shfl_xor_sync(0xffffffffu, mx0, 1));
        mx0 = fmaxf(mx0, __shfl_xor_sync(0xffffffffu, mx0, 2));
        mx1 = fmaxf(mx1, __shfl_xor_sync(0xffffffffu, mx1, 1));
        mx1 = fmaxf(mx1, __shfl_xor_sync(0xffffffffu, mx1, 2));

        float mn0 = fmaxf(m0, mx0), mn1 = fmaxf(m1, mx1);
        float al0 = ex2f((m0 - mn0) * LOG2E);
        float al1 = ex2f((m1 - mn1) * LOG2E);
        const float c0 = mn0 * LOG2E, c1 = mn1 * LOG2E;

        float s0 = 0.f, s1 = 0.f;
        #pragma unroll
        for (int nt = 0; nt < 8; nt++) {
            sc[nt][0] = ex2f(fmaf(sc[nt][0], LOG2E, -c0));
            sc[nt][1] = ex2f(fmaf(sc[nt][1], LOG2E, -c0));
            sc[nt][2] = ex2f(fmaf(sc[nt][2], LOG2E, -c1));
            sc[nt][3] = ex2f(fmaf(sc[nt][3], LOG2E, -c1));
            s0 += sc[nt][0] + sc[nt][1];
            s1 += sc[nt][2] + sc[nt][3];
        }
        s0 += __shfl_xor_sync(0xffffffffu, s0, 1);
        s0 += __shfl_xor_sync(0xffffffffu, s0, 2);
        s1 += __shfl_xor_sync(0xffffffffu, s1, 1);
        s1 += __shfl_xor_sync(0xffffffffu, s1, 2);

        l0 = l0 * al0 + s0;
        l1 = l1 * al1 + s1;
        m0 = mn0; m1 = mn1;

        #pragma unroll
        for (int nt = 0; nt < 8; nt++) {
            o[nt][0] *= al0; o[nt][1] *= al0;
            o[nt][2] *= al1; o[nt][3] *= al1;
        }

        // --- P -> fp16x2 fragments (exact pack) ---
        unsigned pf[16];
        #pragma unroll
        for (int nt = 0; nt < 8; nt++) {
            pf[2 * nt]     = f16x2_of(sc[nt][1], sc[nt][0]);
            pf[2 * nt + 1] = f16x2_of(sc[nt][3], sc[nt][2]);
        }

        // --- O += P V (fp16, single V term) ---
        const uint32_t vbase = uVS + (uint32_t)((v_k * FST + v_n) * 2);
        #pragma unroll
        for (int ch = 0; ch < 4; ++ch) {
            unsigned* af = &pf[4 * ch];
            const uint32_t cOff = (uint32_t)(ch * 16 * FST * 2);
            #pragma unroll
            for (int ntp = 0; ntp < 4; ntp++) {
                unsigned vf[4];
                ldm_x4t(vf, vbase + cOff + (uint32_t)(ntp * 16 * 2));
                unsigned bb0[2] = {vf[0], vf[1]}, bb1[2] = {vf[2], vf[3]};
                mma_f16(o[2 * ntp],     af, bb0);
                mma_f16(o[2 * ntp + 1], af, bb1);
            }
        }
    }

    // --- epilogue: normalize, store single fp16 to g_a [b, s, h, dh] ---
    float i0 = (l0 > 0.f) ? 1.f / l0 : 0.f;
    float i1 = (l1 > 0.f) ? 1.f / l1 : 0.f;
    size_t ob = head_off + (size_t)(qb * 128) * DD;
    #pragma unroll
    for (int nt = 0; nt < 8; nt++) {
        int c = nt * 8 + cq * 2;
        *reinterpret_cast<unsigned*>(g_a + ob + (size_t)row0 * DD + c) =
            f16x2_of(o[nt][1] * i0, o[nt][0] * i0);
        *reinterpret_cast<unsigned*>(g_a + ob + (size_t)(row0 + 8) * DD + c) =
            f16x2_of(o[nt][3] * i1, o[nt][2] * i1);
    }
}

// ---------------------------------------------------------------------------
extern "C" void kernel_launch(void* const* d_in, const int* in_sizes, int n_in,
                              void* d_out, int out_size)
{
    (void)in_sizes; (void)n_in; (void)out_size;
    const float* x  = (const float*)d_in[0];
    const float* Wq = (const float*)d_in[1];
    const float* bq = (const float*)d_in[2];
    const float* Wk = (const float*)d_in[3];
    const float* bk = (const float*)d_in[4];
    const float* Wv = (const float*)d_in[5];
    const float* bv = (const float*)d_in[6];
    const float* Wo = (const float*)d_in[7];
    const float* bo = (const float*)d_in[8];
    const int*   pm = (const int*)d_in[9];
    float* out = (float*)d_out;

    cudaFuncSetAttribute(gemm_k, cudaFuncAttributeMaxDynamicSharedMemorySize, GEMM_SMEM);
    cudaFuncSetAttribute(flash_attn_kernel, cudaFuncAttributeMaxDynamicSharedMemorySize, FLASH_SMEM);

    split_src<<<(BSROWS * DD / 4) / 256, 256>>>(x);
    dim3 wgrid(32, 32, 4);
    wsplit_all<<<wgrid, 256>>>(Wq, Wk, Wv, Wo);

    dim3 qkvgrid(BSROWS / 128, DD / 128, 3);    // (64, 8, 3)
    gemm_k<<<qkvgrid, 256, GEMM_SMEM>>>(bq, bk, bv, nullptr, -1);

    dim3 fgrid(SS / 128, BB * HH);              // (16, 64)
    flash_attn_kernel<<<fgrid, 256, FLASH_SMEM>>>(pm);

    dim3 ogrid(BSROWS / 128, DD / 128, 1);      // (64, 8, 1)
    gemm_k<<<ogrid, 256, GEMM_SMEM>>>(bo, nullptr, nullptr, out, 3);
}

// round 17
// speedup vs baseline: 1.0091x; 1.0091x over previous
#include <cuda_runtime.h>
#include <cuda_bf16.h>
#include <cuda_fp16.h>
#include <cstdint>

// Problem constants
#define BB 4
#define SS 2048
#define DD 1024
#define HH 16
#define DHH 64
#define BSROWS (BB * SS)          // 8192

// ---------------------------------------------------------------------------
// Device-global scratch (allocation-free). All single fp16.
// ---------------------------------------------------------------------------
__device__ __half g_x[(size_t)BSROWS * DD];
__device__ __half g_q[(size_t)BSROWS * DD];
__device__ __half g_k[(size_t)BSROWS * DD];
__device__ __half g_v[(size_t)BSROWS * DD];
__device__ __half g_a[(size_t)BSROWS * DD];
__device__ __half g_wt[4 * (size_t)DD * DD];   // W^T [n][k], single fp16

#define LOG2E 1.4426950408889634f

// ---------------------------------------------------------------------------
// Helpers
// ---------------------------------------------------------------------------
__device__ __forceinline__ void mma_f16(float* c, const unsigned* a, const unsigned* b) {
    asm volatile(
        "mma.sync.aligned.m16n8k16.row.col.f32.f16.f16.f32 "
        "{%0,%1,%2,%3}, {%4,%5,%6,%7}, {%8,%9}, {%0,%1,%2,%3};\n"
        : "+f"(c[0]), "+f"(c[1]), "+f"(c[2]), "+f"(c[3])
        : "r"(a[0]), "r"(a[1]), "r"(a[2]), "r"(a[3]),
          "r"(b[0]), "r"(b[1]));
}

__device__ __forceinline__ void ldm_x4(unsigned* r, uint32_t addr) {
    asm volatile("ldmatrix.sync.aligned.m8n8.x4.shared.b16 {%0,%1,%2,%3}, [%4];"
        : "=r"(r[0]), "=r"(r[1]), "=r"(r[2]), "=r"(r[3]) : "r"(addr));
}
__device__ __forceinline__ void ldm_x4t(unsigned* r, uint32_t addr) {
    asm volatile("ldmatrix.sync.aligned.m8n8.x4.trans.shared.b16 {%0,%1,%2,%3}, [%4];"
        : "=r"(r[0]), "=r"(r[1]), "=r"(r[2]), "=r"(r[3]) : "r"(addr));
}

// f32 pair -> f16x2 (hi arg -> upper half)
__device__ __forceinline__ unsigned f16x2_of(float hi, float lo) {
    unsigned r;
    asm("cvt.rn.f16x2.f32 %0, %1, %2;" : "=r"(r) : "f"(hi), "f"(lo));
    return r;
}
__device__ __forceinline__ float ex2f(float x) {
    float r;
    asm("ex2.approx.ftz.f32 %0, %1;" : "=f"(r) : "f"(x));
    return r;
}

__device__ __forceinline__ void cpa16(void* s, const void* g) {
    unsigned sa = (unsigned)__cvta_generic_to_shared(s);
    asm volatile("cp.async.cg.shared.global [%0], [%1], 16;\n" :: "r"(sa), "l"(g));
}
__device__ __forceinline__ void cpa4(void* s, const void* g) {
    unsigned sa = (unsigned)__cvta_generic_to_shared(s);
    asm volatile("cp.async.ca.shared.global [%0], [%1], 4;\n" :: "r"(sa), "l"(g));
}
__device__ __forceinline__ void cpa_commit() {
    asm volatile("cp.async.commit_group;\n");
}
template <int N>
__device__ __forceinline__ void cpa_wait() {
    asm volatile("cp.async.wait_group %0;\n" :: "n"(N));
}
__device__ __forceinline__ uint32_t smem_u32(const void* p) {
    return (uint32_t)__cvta_generic_to_shared(p);
}

// ---------------------------------------------------------------------------
// Prep: x fp32 -> single fp16
// ---------------------------------------------------------------------------
__global__ __launch_bounds__(256)
void split_src(const float* __restrict__ x)
{
    int i = blockIdx.x * 256 + threadIdx.x;            // over float4s: 2M
    float4 v = reinterpret_cast<const float4*>(x)[i];
    uint2 u;
    u.x = f16x2_of(v.y, v.x);
    u.y = f16x2_of(v.w, v.z);
    reinterpret_cast<uint2*>(g_x)[i] = u;
}

// ---------------------------------------------------------------------------
// Prep: transpose all 4 W [k][n] fp32 -> g_wt[z] as [n][k] single fp16
// ---------------------------------------------------------------------------
__global__ __launch_bounds__(256)
void wsplit_all(const float* __restrict__ W0, const float* __restrict__ W1,
                const float* __restrict__ W2, const float* __restrict__ W3)
{
    const int widx = blockIdx.z;
    const float* W = (widx == 0) ? W0 : (widx == 1) ? W1 : (widx == 2) ? W2 : W3;
    __shared__ float t[32][33];
    const int kb = blockIdx.x * 32, nb = blockIdx.y * 32;
    const int r = threadIdx.x >> 3, c4 = (threadIdx.x & 7) * 4;
    float4 v = *reinterpret_cast<const float4*>(W + (size_t)(kb + r) * DD + nb + c4);
    t[r][c4 + 0] = v.x; t[r][c4 + 1] = v.y; t[r][c4 + 2] = v.z; t[r][c4 + 3] = v.w;
    __syncthreads();
    __half* oh = g_wt + (size_t)widx * DD * DD;
    uint2 uh;
    uh.x = f16x2_of(t[c4 + 1][r], t[c4 + 0][r]);
    uh.y = f16x2_of(t[c4 + 3][r], t[c4 + 2][r]);
    size_t o = (size_t)(nb + r) * DD + kb + c4;
    *reinterpret_cast<uint2*>(oh + o) = uh;
}

// ---------------------------------------------------------------------------
// GEMM (single fp16, m16n8k16 + ldmatrix): C = A * W^T' + bias, M=8192, N=K=1024
// CTA tile 128x128, 8 warps (4 M x 2 N), warp tile 32x64. KS=64, 3-stage
// cp.async pipeline. 2 CTAs/SM. (At mma.sync structural plateau — frozen.)
// mode -1: md=blockIdx.z (Q scaled 1/8; K, V single fp16 out)
// mode  3: A=g_a (attended), out fp32 to outF
// ---------------------------------------------------------------------------
#define KS 64
#define AST 72
#define NSTG 3
#define STAGE (128 * AST)                    // halves per array per stage = 9216
#define SLAB (NSTG * STAGE)                  // halves per array = 27648
#define GEMM_SMEM (2 * SLAB * 2)             // 110592 bytes (sA, sB)

__global__ __launch_bounds__(256, 2)
void gemm_k(const float* __restrict__ b0, const float* __restrict__ b1,
            const float* __restrict__ b2, float* __restrict__ outF, int mode)
{
    const int md = (mode < 0) ? (int)blockIdx.z : mode;
    const __half* A = (md < 3) ? g_x : g_a;
    const __half* Wh = g_wt + (size_t)md * DD * DD;
    const float* bias = (md == 1) ? b1 : (md == 2) ? b2 : b0;
    const float scale = (md == 0) ? 0.125f : 1.0f;

    extern __shared__ __half sm[];
    __half* sA = sm;
    __half* sB = sm + SLAB;
    const uint32_t uA = smem_u32(sA);
    const uint32_t uB = smem_u32(sB);

    const int tid  = threadIdx.x;
    const int lane = tid & 31;
    const int warp = tid >> 5;
    const int wm = warp & 3, wn = warp >> 2;
    const int cm = blockIdx.x * 128, cn = blockIdx.y * 128;
    const int rq = lane >> 2, cq = lane & 3;

    // ldmatrix lane->row mappings
    const int a_r = lane & 15, a_k = (lane >> 4) * 8;               // A x4
    const int b_n = ((lane >> 3) & 1) * 8 + (lane & 7);             // B x4 (pair of n-tiles)
    const int b_k = (lane >> 4) * 8;

    // stage kt (64 k-columns) into buffer buf
    auto issue = [&](int kt, int buf) {
        const int k0 = kt * KS;
        #pragma unroll
        for (int i = 0; i < 4; i++) {                // A: 128 rows
            int idx = i * 256 + tid;
            int r = idx >> 3, c8 = (idx & 7) * 8;
            size_t ga = (size_t)(cm + r) * DD + k0 + c8;
            int so = buf * STAGE + r * AST + c8;
            cpa16(&sA[so], A + ga);
        }
        #pragma unroll
        for (int i = 0; i < 4; i++) {                // B: 128 rows
            int idx = i * 256 + tid;
            int r = idx >> 3, c8 = (idx & 7) * 8;
            size_t gb = (size_t)(cn + r) * DD + k0 + c8;
            int so = buf * STAGE + r * AST + c8;
            cpa16(&sB[so], Wh + gb);
        }
        cpa_commit();
    };

    float acc[2][8][4];
    #pragma unroll
    for (int mt = 0; mt < 2; mt++)
        #pragma unroll
        for (int nt = 0; nt < 8; nt++)
            #pragma unroll
            for (int j = 0; j < 4; j++) acc[mt][nt][j] = 0.f;

    const int NK = DD / KS;  // 16
    issue(0, 0);
    issue(1, 1);

    int cur = 0;
    for (int kt = 0; kt < NK; ++kt) {
        if (kt + 1 < NK) cpa_wait<1>();
        else             cpa_wait<0>();
        __syncthreads();            // data visible; readers of buffer (kt+2)%3 retired
        if (kt + 2 < NK) issue(kt + 2, (cur + 2 >= NSTG) ? cur + 2 - NSTG : cur + 2);

        const uint32_t bufOff = (uint32_t)(cur * STAGE * 2);
        const uint32_t abase = uA + bufOff + (uint32_t)(((wm * 32 + a_r) * AST + a_k) * 2);
        const uint32_t bbase = uB + bufOff + (uint32_t)(((wn * 64 + b_n) * AST + b_k) * 2);
        #pragma unroll
        for (int ch = 0; ch < 4; ++ch) {
            const uint32_t kc2 = (uint32_t)(ch * 32);   // 16 halves per chunk
            unsigned ah[2][4];
            #pragma unroll
            for (int mt = 0; mt < 2; mt++)
                ldm_x4(ah[mt], abase + (uint32_t)(mt * 16 * AST * 2) + kc2);
            #pragma unroll
            for (int ntp = 0; ntp < 4; ntp++) {
                unsigned kf[4];
                ldm_x4(kf, bbase + (uint32_t)(ntp * 16 * AST * 2) + kc2);
                unsigned bb0[2] = {kf[0], kf[2]}, bb1[2] = {kf[1], kf[3]};
                mma_f16(acc[0][2 * ntp],     ah[0], bb0);
                mma_f16(acc[1][2 * ntp],     ah[1], bb0);
                mma_f16(acc[0][2 * ntp + 1], ah[0], bb1);
                mma_f16(acc[1][2 * ntp + 1], ah[1], bb1);
            }
        }
        cur = (cur + 1 >= NSTG) ? 0 : cur + 1;
    }

    // epilogue
    #pragma unroll
    for (int mt = 0; mt < 2; mt++) {
        int r = cm + wm * 32 + mt * 16 + rq;
        #pragma unroll
        for (int nt = 0; nt < 8; nt++) {
            int c = cn + wn * 64 + nt * 8 + cq * 2;
            float bb0 = bias[c], bb1 = bias[c + 1];
            float v0 = (acc[mt][nt][0] + bb0) * scale;
            float v1 = (acc[mt][nt][1] + bb1) * scale;
            float v2 = (acc[mt][nt][2] + bb0) * scale;
            float v3 = (acc[mt][nt][3] + bb1) * scale;
            if (md == 3) {
                *reinterpret_cast<float2*>(outF + (size_t)r * DD + c) = make_float2(v0, v1);
                *reinterpret_cast<float2*>(outF + (size_t)(r + 8) * DD + c) = make_float2(v2, v3);
            } else {                // Q (pre-scaled) / K / V: single fp16
                __half* O = (md == 0) ? g_q : (md == 1) ? g_k : g_v;
                *reinterpret_cast<unsigned*>(O + (size_t)r * DD + c) = f16x2_of(v1, v0);
                *reinterpret_cast<unsigned*>(O + (size_t)(r + 8) * DD + c) = f16x2_of(v3, v2);
            }
        }
    }
}

// ---------------------------------------------------------------------------
// Flash attention, 128-row Q tiles, 8 warps. 128-row KV iterations (two
// 64-column halves per wait/sync/issue — halves per-iteration fixed overhead).
// QK: fp16 x fp16. PV: fp16 P x fp16 V.
// smem halves: Q (128xFST) | K0,K1 (128xFST) | V0,V1 (128xFST) | Ms[2][128]
// ---------------------------------------------------------------------------
#define FST 72                                // smem k-stride (halves)
#define K128 (128 * FST)                      // halves per 128-row array
#define QFQ (128 * FST)                       // Q halves
#define KOFF QFQ
#define VOFF (QFQ + 2 * K128)
#define FLASH_SMEM ((QFQ + 4 * K128) * 2 + 2 * 128 * 4)   // 93184 bytes

__global__ __launch_bounds__(256, 2)
void flash_attn_kernel(const int* __restrict__ pmask)
{
    extern __shared__ __half fsm[];
    int* Ms0 = reinterpret_cast<int*>(fsm + QFQ + 4 * K128);
    const uint32_t uQ = smem_u32(fsm);

    const int tid = threadIdx.x, lane = tid & 31, warp = tid >> 5;
    const int qb = (int)(gridDim.x - 1) - (int)blockIdx.x;  // heavy tiles first
    const int bh = blockIdx.y;
    const int b = bh >> 4, h = bh & 15;
    const size_t head_off = ((size_t)b * SS) * DD + (size_t)h * DHH;
    const int nit = qb + 1;                   // 128-wide KV iterations

    const int rq = lane >> 2, cq = lane & 3;
    const int row0 = warp * 16 + rq;
    const int rowmax = qb * 128 + warp * 16 + 15;   // last query row of this warp

    // ldmatrix lane->row mappings
    const int a_r = lane & 15, a_k = (lane >> 4) * 8;      // Q (A, x4)
    const int b_n = ((lane >> 3) & 1) * 8 + (lane & 7);    // K (B, x4 pair)
    const int b_k = (lane >> 4) * 8;
    const int v_k = ((lane >> 3) & 1) * 8 + (lane & 7);    // V (B^T via x4.trans)
    const int v_n = (lane >> 4) * 8;

    // KV rows [it*128, it*128+128) + mask into buffers (it&1); one group
    auto issueKV = [&](int it) {
        const int bsel = it & 1;
        __half* KH = fsm + KOFF + K128 * bsel;
        __half* VS = fsm + VOFF + K128 * bsel;
        #pragma unroll
        for (int i = 0; i < 4; i++) {
            int idx = i * 256 + tid;
            int r = idx >> 3, c8 = (idx & 7) * 8;
            size_t g = head_off + (size_t)(it * 128 + r) * DD + c8;
            cpa16(&KH[r * FST + c8], g_k + g);
            cpa16(&VS[r * FST + c8], g_v + g);
        }
        if (tid < 128) cpa4(&Ms0[bsel * 128 + tid], pmask + b * SS + it * 128 + tid);
        cpa_commit();
    };

    // Prologue: Q (128x64) + KV(0)/mask0 in ONE group
    #pragma unroll
    for (int i = 0; i < 4; i++) {
        int idx = i * 256 + tid;
        int r = idx >> 3, c8 = (idx & 7) * 8;
        size_t g = head_off + (size_t)(qb * 128 + r) * DD + c8;
        cpa16(&fsm[r * FST + c8], g_q + g);
    }
    {
        __half* KH = fsm + KOFF;
        __half* VS = fsm + VOFF;
        #pragma unroll
        for (int i = 0; i < 4; i++) {
            int idx = i * 256 + tid;
            int r = idx >> 3, c8 = (idx & 7) * 8;
            size_t g = head_off + (size_t)r * DD + c8;
            cpa16(&KH[r * FST + c8], g_k + g);
            cpa16(&VS[r * FST + c8], g_v + g);
        }
        if (tid < 128) cpa4(&Ms0[tid], pmask + b * SS + tid);
        cpa_commit();
    }

    float o[8][4];
    #pragma unroll
    for (int nt = 0; nt < 8; nt++)
        #pragma unroll
        for (int j = 0; j < 4; j++) o[nt][j] = 0.f;
    float m0 = -1e30f, m1 = -1e30f, l0 = 0.f, l1 = 0.f;

    const uint32_t qbase = uQ + (uint32_t)(((warp * 16 + a_r) * FST + a_k) * 2);

    for (int it = 0; it < nit; ++it) {
        cpa_wait<0>();
        __syncthreads();
        if (it + 1 < nit) issueKV(it + 1);

        const int bsel = it & 1;
        const uint32_t uKH = smem_u32(fsm + KOFF + K128 * bsel);
        const uint32_t uVS = smem_u32(fsm + VOFF + K128 * bsel);

        #pragma unroll
        for (int h2 = 0; h2 < 2; ++h2) {
            const int kb = 2 * it + h2;
            // per-warp skip: entire 64-wide block above this warp's rows
            if (kb * 64 > rowmax) continue;

            const int* Ms = Ms0 + bsel * 128 + h2 * 64;
            const uint32_t hOff = (uint32_t)(h2 * 64 * FST * 2);

            // mask fast-path detection (warp-uniform)
            unsigned mw0 = __ballot_sync(0xffffffffu, Ms[lane] != 0);
            unsigned mw1 = __ballot_sync(0xffffffffu, Ms[32 + lane] != 0);
            const bool needmask = ((mw0 & mw1) != 0xffffffffu) ||
                                  (kb * 64 + 63 > qb * 128 + warp * 16);

            // --- S = Q K^T (warp: 16 x 64), single-term fp16 ---
            float sc[8][4];
            #pragma unroll
            for (int nt = 0; nt < 8; nt++)
                #pragma unroll
                for (int j = 0; j < 4; j++) sc[nt][j] = 0.f;

            const uint32_t kbase = uKH + hOff + (uint32_t)((b_n * FST + b_k) * 2);
            #pragma unroll
            for (int ch = 0; ch < 4; ++ch) {
                const uint32_t kc2 = (uint32_t)(ch * 32);
                unsigned ah[4];
                ldm_x4(ah, qbase + kc2);
                #pragma unroll
                for (int ntp = 0; ntp < 4; ntp++) {
                    unsigned kf[4];
                    ldm_x4(kf, kbase + (uint32_t)(ntp * 16 * FST * 2) + kc2);
                    unsigned bb0[2] = {kf[0], kf[2]}, bb1[2] = {kf[1], kf[3]};
                    mma_f16(sc[2 * ntp],     ah, bb0);
                    mma_f16(sc[2 * ntp + 1], ah, bb1);
                }
            }

            // --- mask (slow path only; Q pre-scaled; sentinel -1e30) ---
            if (needmask) {
                const int gm0 = qb * 128 + row0, gm1 = gm0 + 8;
                #pragma unroll
                for (int nt = 0; nt < 8; nt++) {
                    int nloc = nt * 8 + cq * 2;
                    int gn = kb * 64 + nloc;
                    #pragma unroll
                    for (int j = 0; j < 2; j++) {
                        bool pv = (Ms[nloc + j] != 0);
                        sc[nt][j]     = (pv && (gn + j) <= gm0) ? sc[nt][j]     : -1e30f;
                        sc[nt][2 + j] = (pv && (gn + j) <= gm1) ? sc[nt][2 + j] : -1e30f;
                    }
                }
            }

            // --- online softmax ---
            float mx0 = -1e30f, mx1 = -1e30f;
            #pragma unroll
            for (int nt = 0; nt < 8; nt++) {
                mx0 = fmaxf(mx0, fmaxf(sc[nt][0], sc[nt][1]));
                mx1 = fmaxf(mx1, fmaxf(sc[nt][2], sc[nt][3]));
            }
            mx0 = fmaxf(mx0, __shfl_xor_sync(0xffffffffu, mx0, 1));
            mx0 = fmaxf(mx0, __shfl_xor_sync(0xffffffffu, mx0, 2));
            mx1 = fmaxf(mx1, __shfl_xor_sync(0xffffffffu, mx1, 1));
            mx1 = fmaxf(mx1, __shfl_xor_sync(0xffffffffu, mx1, 2));

            float mn0 = fmaxf(m0, mx0), mn1 = fmaxf(m1, mx1);
            float al0 = ex2f((m0 - mn0) * LOG2E);
            float al1 = ex2f((m1 - mn1) * LOG2E);
            const float c0 = mn0 * LOG2E, c1 = mn1 * LOG2E;

            float s0 = 0.f, s1 = 0.f;
            #pragma unroll
            for (int nt = 0; nt < 8; nt++) {
                sc[nt][0] = ex2f(fmaf(sc[nt][0], LOG2E, -c0));
                sc[nt][1] = ex2f(fmaf(sc[nt][1], LOG2E, -c0));
                sc[nt][2] = ex2f(fmaf(sc[nt][2], LOG2E, -c1));
                sc[nt][3] = ex2f(fmaf(sc[nt][3], LOG2E, -c1));
                s0 += sc[nt][0] + sc[nt][1];
                s1 += sc[nt][2] + sc[nt][3];
            }
            s0 += __shfl_xor_sync(0xffffffffu, s0, 1);
            s0 += __shfl_xor_sync(0xffffffffu, s0, 2);
            s1 += __shfl_xor_sync(0xffffffffu, s1, 1);
            s1 += __shfl_xor_sync(0xffffffffu, s1, 2);

            l0 = l0 * al0 + s0;
            l1 = l1 * al1 + s1;
            m0 = mn0; m1 = mn1;

            #pragma unroll
            for (int nt = 0; nt < 8; nt++) {
                o[nt][0] *= al0; o[nt][1] *= al0;
                o[nt][2] *= al1; o[nt][3] *= al1;
            }

            // --- P -> fp16x2 fragments (exact pack) ---
            unsigned pf[16];
            #pragma unroll
            for (int nt = 0; nt < 8; nt++) {
                pf[2 * nt]     = f16x2_of(sc[nt][1], sc[nt][0]);
                pf[2 * nt + 1] = f16x2_of(sc[nt][3], sc[nt][2]);
            }

            // --- O += P V (fp16, single V term) ---
            const uint32_t vbase = uVS + hOff + (uint32_t)((v_k * FST + v_n) * 2);
            #pragma unroll
            for (int ch = 0; ch < 4; ++ch) {
                unsigned* af = &pf[4 * ch];
                const uint32_t cOff = (uint32_t)(ch * 16 * FST * 2);
                #pragma unroll
                for (int ntp = 0; ntp < 4; ntp++) {
                    unsigned vf[4];
                    ldm_x4t(vf, vbase + cOff + (uint32_t)(ntp * 16 * 2));
                    unsigned bb0[2] = {vf[0], vf[1]}, bb1[2] = {vf[2], vf[3]};
                    mma_f16(o[2 * ntp],     af, bb0);
                    mma_f16(o[2 * ntp + 1], af, bb1);
                }
            }
        }
    }

    // --- epilogue: normalize, store single fp16 to g_a [b, s, h, dh] ---
    float i0 = (l0 > 0.f) ? 1.f / l0 : 0.f;
    float i1 = (l1 > 0.f) ? 1.f / l1 : 0.f;
    size_t ob = head_off + (size_t)(qb * 128) * DD;
    #pragma unroll
    for (int nt = 0; nt < 8; nt++) {
        int c = nt * 8 + cq * 2;
        *reinterpret_cast<unsigned*>(g_a + ob + (size_t)row0 * DD + c) =
            f16x2_of(o[nt][1] * i0, o[nt][0] * i0);
        *reinterpret_cast<unsigned*>(g_a + ob + (size_t)(row0 + 8) * DD + c) =
            f16x2_of(o[nt][3] * i1, o[nt][2] * i1);
    }
}

// ---------------------------------------------------------------------------
extern "C" void kernel_launch(void* const* d_in, const int* in_sizes, int n_in,
                              void* d_out, int out_size)
{
    (void)in_sizes; (void)n_in; (void)out_size;
    const float* x  = (const float*)d_in[0];
    const float* Wq = (const float*)d_in[1];
    const float* bq = (const float*)d_in[2];
    const float* Wk = (const float*)d_in[3];
    const float* bk = (const float*)d_in[4];
    const float* Wv = (const float*)d_in[5];
    const float* bv = (const float*)d_in[6];
    const float* Wo = (const float*)d_in[7];
    const float* bo = (const float*)d_in[8];
    const int*   pm = (const int*)d_in[9];
    float* out = (float*)d_out;

    cudaFuncSetAttribute(gemm_k, cudaFuncAttributeMaxDynamicSharedMemorySize, GEMM_SMEM);
    cudaFuncSetAttribute(flash_attn_kernel, cudaFuncAttributeMaxDynamicSharedMemorySize, FLASH_SMEM);

    split_src<<<(BSROWS * DD / 4) / 256, 256>>>(x);
    dim3 wgrid(32, 32, 4);
    wsplit_all<<<wgrid, 256>>>(Wq, Wk, Wv, Wo);

    dim3 qkvgrid(BSROWS / 128, DD / 128, 3);    // (64, 8, 3)
    gemm_k<<<qkvgrid, 256, GEMM_SMEM>>>(bq, bk, bv, nullptr, -1);

    dim3 fgrid(SS / 128, BB * HH);              // (16, 64)
    flash_attn_kernel<<<fgrid, 256, FLASH_SMEM>>>(pm);

    dim3 ogrid(BSROWS / 128, DD / 128, 1);      // (64, 8, 1)
    gemm_k<<<ogrid, 256, GEMM_SMEM>>>(bo, nullptr, nullptr, out, 3);
}